// round 15
// baseline (speedup 1.0000x reference)
#include <cuda_runtime.h>
#include <math.h>

// CMPNN layer: fused edge pipeline + atomic aggregation + fused node pipeline.
// R15: 512 threads/CTA (4 warps/SMSP) + packed fp32x2 FFMA2 inner loops.
// Shapes (fixed): N=50000, E=800000, ND=ED=64, HD=192.
//
// Output: [update_nodes (N*64) | update_edges (E*64)] float32.

#define MAXN 50000
__device__ float g_aggsum[MAXN * 128];   // segment_sum of m = [h_src, e']
__device__ int   g_aggmax[MAXN * 128];   // segment_max, order-preserving int encoding

#define NT 512   // threads per CTA

static __device__ __forceinline__ int enc_f2i(float v) {
    int iv = __float_as_int(v);
    return iv >= 0 ? iv : (iv ^ 0x7FFFFFFF);
}
static __device__ __forceinline__ float dec_i2f(int key) {
    int iv = key >= 0 ? key : (key ^ 0x7FFFFFFF);
    return __int_as_float(iv);
}

// ---- packed f32x2 helpers (Blackwell FFMA2 path; ptxas never emits these) ----
typedef unsigned long long u64t;

static __device__ __forceinline__ u64t bcast2(float x) {
    u64t r; asm("mov.b64 %0, {%1, %1};" : "=l"(r) : "f"(x)); return r;
}
static __device__ __forceinline__ void unpk2(float& lo, float& hi, u64t v) {
    asm("mov.b64 {%0, %1}, %2;" : "=f"(lo), "=f"(hi) : "l"(v));
}
#define FMA2(d, a, b, c) \
    asm("fma.rn.f32x2 %0, %1, %2, %3;" : "=l"(d) : "l"(a), "l"(b), "l"(c))

__global__ void init_agg_kernel(int total) {
    int i = blockIdx.x * blockDim.x + threadIdx.x;
    if (i < total) {
        g_aggsum[i] = 0.0f;
        g_aggmax[i] = INT_MIN;   // < enc(-inf); decodes to NaN -> treated as empty
    }
}

// ---------------------------------------------------------------------------
// Shared-memory tiled GEMM:  Cs[64][NC] = As[64][KTOT] @ Wg[NC][KTOT]^T + bias
// 512 threads as 16x32 grid. Thread (tx,ty) owns rows ty*2..+1 and column
// PAIRS {32p+2tx, 32p+2tx+1}, p=0..NC/32-1, accumulated in packed f32x2.
// Weights staged K-major in smem: Ws[kk][col], pitch NC+2.
// ---------------------------------------------------------------------------
template<int NC, int KTOT, int LDA, int LDC>
static __device__ __forceinline__ void gemm_tile(
    const float* __restrict__ Wg, const float* __restrict__ bias,
    const float* __restrict__ As, float* __restrict__ Cs, float* Ws,
    int tid, int tx, int ty)
{
    constexpr int NP = NC / 32;       // f32x2 pairs per thread
    constexpr int WP = NC + 2;        // Ws pitch in floats (even -> 8B aligned rows)
    u64t acc2[2][NP];
    #pragma unroll
    for (int i = 0; i < 2; i++)
        #pragma unroll
        for (int p = 0; p < NP; p++) acc2[i][p] = 0ull;

    for (int k0 = 0; k0 < KTOT; k0 += 64) {
        for (int idx = tid; idx < NC * 64; idx += NT) {
            int col = idx >> 6, kk = idx & 63;
            Ws[kk * WP + col] = Wg[col * KTOT + k0 + kk];
        }
        __syncthreads();
        const float* Ab = As + ty * 2 * LDA + k0;
        #pragma unroll 4
        for (int kk = 0; kk < 64; ++kk) {
            u64t a2[2];
            #pragma unroll
            for (int i = 0; i < 2; i++) a2[i] = bcast2(Ab[i * LDA + kk]);
            const u64t* Wr = (const u64t*)(Ws + kk * WP) + tx;
            #pragma unroll
            for (int p = 0; p < NP; p++) {
                u64t w2 = Wr[p * 16];
                #pragma unroll
                for (int i = 0; i < 2; i++) FMA2(acc2[i][p], a2[i], w2, acc2[i][p]);
            }
        }
        __syncthreads();
    }
    #pragma unroll
    for (int p = 0; p < NP; p++) {
        int c0 = 32 * p + 2 * tx;
        float b0 = bias[c0], b1v = bias[c0 + 1];
        #pragma unroll
        for (int i = 0; i < 2; i++) {
            float lo, hi; unpk2(lo, hi, acc2[i][p]);
            float* crow = Cs + (ty * 2 + i) * LDC + c0;
            crow[0] = lo + b0;
            crow[1] = hi + b1v;
        }
    }
    __syncthreads();
}

// Small GEMM: packed acc2[2][2] = As[64][64] @ Wg[64][64]^T, result in registers.
template<int LDA>
static __device__ __forceinline__ void gemm64_pair(
    const float* __restrict__ Wg, const float* __restrict__ As,
    float* Ws, u64t acc2[2][2], int tid, int tx, int ty)
{
    constexpr int WP = 66;
    #pragma unroll
    for (int i = 0; i < 2; i++)
        #pragma unroll
        for (int p = 0; p < 2; p++) acc2[i][p] = 0ull;
    for (int idx = tid; idx < 64 * 64; idx += NT)
        Ws[(idx & 63) * WP + (idx >> 6)] = Wg[idx];
    __syncthreads();
    const float* Ab = As + ty * 2 * LDA;
    #pragma unroll 4
    for (int kk = 0; kk < 64; ++kk) {
        u64t a2[2];
        #pragma unroll
        for (int i = 0; i < 2; i++) a2[i] = bcast2(Ab[i * LDA + kk]);
        const u64t* Wr = (const u64t*)(Ws + kk * WP) + tx;
        #pragma unroll
        for (int p = 0; p < 2; p++) {
            u64t w2 = Wr[p * 16];
            #pragma unroll
            for (int i = 0; i < 2; i++) FMA2(acc2[i][p], a2[i], w2, acc2[i][p]);
        }
    }
    __syncthreads();
}

static __device__ __forceinline__ float sigm(float x) { return 1.0f / (1.0f + expf(-x)); }

// LayerNorm(192) + affine + LeakyReLU(0.2), in place on Bs (pitch 196).
static __device__ __forceinline__ void ln_leaky(
    float* Bs, float* muA, float* rsA,
    const float* __restrict__ lng, const float* __restrict__ lnb,
    int tid, int tx, int ty)
{
    // 128 threads: 2 per row, each sums half the 192 cols, combine via smem.
    if (tid < 128) {
        int r = tid >> 1, half = tid & 1;
        const float* row = Bs + r * 196 + half * 96;
        float s = 0.0f, s2 = 0.0f;
        #pragma unroll 4
        for (int k = 0; k < 96; k++) { float v = row[k]; s += v; s2 = fmaf(v, v, s2); }
        // stash partial in muA/rsA: [0]=even half sums
        if (half == 0) { muA[r] = s; rsA[r] = s2; }
        __syncwarp();
        if (half == 1) {
            float st = muA[r] + s, s2t = rsA[r] + s2;
            float mu = st * (1.0f / 192.0f);
            float var = s2t * (1.0f / 192.0f) - mu * mu;
            muA[r] = mu;
            rsA[r] = rsqrtf(var + 1e-5f);
        }
    }
    __syncthreads();
    #pragma unroll
    for (int i = 0; i < 2; i++) {
        int r = ty * 2 + i;
        float mu = muA[r], rs = rsA[r];
        #pragma unroll
        for (int p = 0; p < 6; p++) {
            #pragma unroll
            for (int l = 0; l < 2; l++) {
                int c = 32 * p + 2 * tx + l;
                float v = Bs[r * 196 + c];
                v = (v - mu) * rs * lng[c] + lnb[c];
                Bs[r * 196 + c] = v > 0.0f ? v : 0.2f * v;
            }
        }
    }
    __syncthreads();
}

// ---------------------------------------------------------------------------
// Edge pipeline: 64 edges / CTA, 512 threads
// smem floats: A[64*196] B[64*196] W[64*194] HE[64*132] mu[64] rs[64] src/dst[128]
// ---------------------------------------------------------------------------
#define EDGE_SMEM_FLOATS (12544 + 12544 + 12416 + 8448 + 64 + 64 + 128)

__global__ __launch_bounds__(NT, 1) void edge_kernel(
    const float* __restrict__ nf, const float* __restrict__ ef,
    const int* __restrict__ src, const int* __restrict__ dst,
    const float* __restrict__ W1e, const float* __restrict__ b1,
    const float* __restrict__ lng, const float* __restrict__ lnb,
    const float* __restrict__ W2, const float* __restrict__ b2,
    const float* __restrict__ Wih, const float* __restrict__ Whh,
    const float* __restrict__ bih, const float* __restrict__ bhh,
    const float* __restrict__ Wre, const float* __restrict__ bre,
    float* __restrict__ out_edges, int E)
{
    extern __shared__ float sm[];
    float* A  = sm;                    // [64][196]
    float* B  = A + 64 * 196;          // [64][196]
    float* W  = B + 64 * 196;          // [64][194] K-major weight stage
    float* HE = W + 64 * 194;          // [64][132]: cols 0:64 h_src, 64:128 e / e'
    float* muA = HE + 64 * 132;
    float* rsA = muA + 64;
    int* srcS = (int*)(rsA + 64);
    int* dstS = srcS + 64;

    const int tid = threadIdx.x, tx = tid & 15, ty = tid >> 4;
    const int eg0 = blockIdx.x * 64;

    if (tid < 64) {
        int e = eg0 + tid;
        srcS[tid] = e < E ? src[e] : 0;
        dstS[tid] = e < E ? dst[e] : 0;
    }
    __syncthreads();

    // Gather msg = [h_src, h_dst, edge_feats] into A; keep [h_src, e] in HE.
    const float4* nf4 = (const float4*)nf;
    const float4* ef4 = (const float4*)ef;
    for (int idx = tid; idx < 64 * 48; idx += NT) {
        int e = idx / 48, q = idx % 48;
        bool valid = (eg0 + e) < E;
        float4 v = make_float4(0.f, 0.f, 0.f, 0.f);
        if (q < 16) {
            if (valid) v = nf4[srcS[e] * 16 + q];
            ((float4*)(HE + e * 132))[q] = v;
        } else if (q < 32) {
            if (valid) v = nf4[dstS[e] * 16 + (q - 16)];
        } else {
            if (valid) v = ef4[(size_t)(eg0 + e) * 16 + (q - 32)];
            ((float4*)(HE + e * 132))[q - 16] = v;
        }
        ((float4*)(A + e * 196))[q] = v;
    }
    __syncthreads();

    // msg_booster: Linear -> LN -> LeakyReLU(0.2) -> Linear
    gemm_tile<192, 192, 196, 196>(W1e, b1, A, B, W, tid, tx, ty);
    ln_leaky(B, muA, rsA, lng, lnb, tid, tx, ty);
    gemm_tile<192, 192, 196, 196>(W2, b2, B, A, W, tid, tx, ty);   // A = edge_input
    // GRU gates
    gemm_tile<192, 192, 196, 196>(Wih, bih, A, B, W, tid, tx, ty); // B = gi
    gemm_tile<192,  64, 132, 196>(Whh, bhh, HE + 64, A, W, tid, tx, ty); // A = gh
    // residual edge_feats @ Wre^T
    u64t accg[2][2];
    gemm64_pair<132>(Wre, HE + 64, W, accg, tid, tx, ty);

    // GRU epilogue + residual + LeakyReLU(0.01); write e', stash in HE[64:128]
    #pragma unroll
    for (int i = 0; i < 2; i++) {
        int e = ty * 2 + i;
        bool valid = (eg0 + e) < E;
        #pragma unroll
        for (int p = 0; p < 2; p++) {
            float rlo, rhi; unpk2(rlo, rhi, accg[i][p]);
            float rr[2] = {rlo, rhi};
            #pragma unroll
            for (int l = 0; l < 2; l++) {
                int c = 32 * p + 2 * tx + l;
                float gir = B[e * 196 + c], giz = B[e * 196 + 64 + c], gin = B[e * 196 + 128 + c];
                float ghr = A[e * 196 + c], ghz = A[e * 196 + 64 + c], ghn = A[e * 196 + 128 + c];
                float efv = HE[e * 132 + 64 + c];
                float r = sigm(gir + ghr);
                float z = sigm(giz + ghz);
                float n = tanhf(fmaf(r, ghn, gin));
                float h = (1.0f - z) * n + z * efv;
                float res = h + rr[l] + bre[c];
                float ue = res > 0.0f ? res : 0.01f * res;
                if (valid) out_edges[(size_t)(eg0 + e) * 64 + c] = ue;
                HE[e * 132 + 64 + c] = ue;
            }
        }
    }
    __syncthreads();

    // Aggregate m = [h_src, e'] at dst: sum + max.
    for (int idx = tid; idx < 64 * 128; idx += NT) {
        int e = idx >> 7, c = idx & 127;
        if ((eg0 + e) < E) {
            int d = dstS[e];
            float v = HE[e * 132 + c];
            atomicAdd(&g_aggsum[d * 128 + c], v);
            atomicMax(&g_aggmax[d * 128 + c], enc_f2i(v));
        }
    }
}

// ---------------------------------------------------------------------------
// Node pipeline: 64 nodes / CTA, 512 threads
// smem floats: A[64*260] B[64*196] W[64*194] NF[64*68] mu[64] rs[64]
// ---------------------------------------------------------------------------
#define NODE_SMEM_FLOATS (16640 + 12544 + 12416 + 4352 + 64 + 64)

__global__ __launch_bounds__(NT, 1) void node_kernel(
    const float* __restrict__ nf,
    const float* __restrict__ W1n, const float* __restrict__ b1,
    const float* __restrict__ lng, const float* __restrict__ lnb,
    const float* __restrict__ W2, const float* __restrict__ b2,
    const float* __restrict__ Wih, const float* __restrict__ Whh,
    const float* __restrict__ bih, const float* __restrict__ bhh,
    const float* __restrict__ Wra, const float* __restrict__ bra,
    float* __restrict__ out_nodes, int N)
{
    extern __shared__ float sm[];
    float* A  = sm;                    // [64][260] : agg = [sum(128) | max(128)]
    float* B  = A + 64 * 260;          // [64][196]
    float* W  = B + 64 * 196;          // [64][194]
    float* NF = W + 64 * 194;          // [64][68]  : node_feats
    float* muA = NF + 64 * 68;
    float* rsA = muA + 64;

    const int tid = threadIdx.x, tx = tid & 15, ty = tid >> 4;
    const int n0 = blockIdx.x * 64;

    for (int idx = tid; idx < 64 * 128; idx += NT) {
        int r = idx >> 7, c = idx & 127;
        int n = n0 + r;
        float s = 0.0f, m = 0.0f;
        if (n < N) {
            s = g_aggsum[n * 128 + c];
            float dm = dec_i2f(g_aggmax[n * 128 + c]);
            m = isfinite(dm) ? dm : 0.0f;   // empty mailbox -> 0
        }
        A[r * 260 + c] = s;
        A[r * 260 + 128 + c] = m;
    }
    for (int idx = tid; idx < 64 * 64; idx += NT) {
        int r = idx >> 6, c = idx & 63;
        NF[r * 68 + c] = (n0 + r) < N ? nf[(size_t)(n0 + r) * 64 + c] : 0.0f;
    }
    __syncthreads();

    gemm_tile<192, 256, 260, 196>(W1n, b1, A, B, W, tid, tx, ty);
    ln_leaky(B, muA, rsA, lng, lnb, tid, tx, ty);
    gemm_tile<192, 192, 196, 260>(W2, b2, B, A, W, tid, tx, ty);   // A = node_input
    gemm_tile<192, 192, 260, 196>(Wih, bih, A, B, W, tid, tx, ty); // B = gi
    gemm_tile<192,  64,  68, 260>(Whh, bhh, NF, A, W, tid, tx, ty); // A = gh
    u64t accg[2][2];
    gemm64_pair<68>(Wra, NF, W, accg, tid, tx, ty);

    #pragma unroll
    for (int i = 0; i < 2; i++) {
        int e = ty * 2 + i;
        if ((n0 + e) >= N) continue;
        #pragma unroll
        for (int p = 0; p < 2; p++) {
            float rlo, rhi; unpk2(rlo, rhi, accg[i][p]);
            float rr[2] = {rlo, rhi};
            #pragma unroll
            for (int l = 0; l < 2; l++) {
                int c = 32 * p + 2 * tx + l;
                float gir = B[e * 196 + c], giz = B[e * 196 + 64 + c], gin = B[e * 196 + 128 + c];
                float ghr = A[e * 260 + c], ghz = A[e * 260 + 64 + c], ghn = A[e * 260 + 128 + c];
                float hv = NF[e * 68 + c];
                float r = sigm(gir + ghr);
                float z = sigm(giz + ghz);
                float n = tanhf(fmaf(r, ghn, gin));
                float h = (1.0f - z) * n + z * hv;
                float res = h + rr[l] + bra[c];
                out_nodes[(size_t)(n0 + e) * 64 + c] = res > 0.0f ? res : 0.01f * res;
            }
        }
    }
}

extern "C" void kernel_launch(void* const* d_in, const int* in_sizes, int n_in,
                              void* d_out, int out_size)
{
    const float* nf   = (const float*)d_in[0];
    const float* ef   = (const float*)d_in[1];
    const int*   src  = (const int*)d_in[2];
    const int*   dst  = (const int*)d_in[3];
    const float* W1e  = (const float*)d_in[4];
    const float* W1n  = (const float*)d_in[5];
    const float* b1   = (const float*)d_in[6];
    const float* lng  = (const float*)d_in[7];
    const float* lnb  = (const float*)d_in[8];
    const float* W2   = (const float*)d_in[9];
    const float* b2   = (const float*)d_in[10];
    const float* Wih_e = (const float*)d_in[11];
    const float* Whh_e = (const float*)d_in[12];
    const float* bih_e = (const float*)d_in[13];
    const float* bhh_e = (const float*)d_in[14];
    const float* Wih_a = (const float*)d_in[15];
    const float* Whh_a = (const float*)d_in[16];
    const float* bih_a = (const float*)d_in[17];
    const float* bhh_a = (const float*)d_in[18];
    const float* Wre  = (const float*)d_in[19];
    const float* bre  = (const float*)d_in[20];
    const float* Wra  = (const float*)d_in[21];
    const float* bra  = (const float*)d_in[22];

    const int N = in_sizes[0] / 64;
    const int E = in_sizes[2];

    float* out_nodes = (float*)d_out;
    float* out_edges = out_nodes + (size_t)N * 64;

    const int edge_smem = EDGE_SMEM_FLOATS * 4;
    const int node_smem = NODE_SMEM_FLOATS * 4;
    cudaFuncSetAttribute(edge_kernel, cudaFuncAttributeMaxDynamicSharedMemorySize, edge_smem);
    cudaFuncSetAttribute(node_kernel, cudaFuncAttributeMaxDynamicSharedMemorySize, node_smem);

    int aggTotal = N * 128;
    init_agg_kernel<<<(aggTotal + 255) / 256, 256>>>(aggTotal);

    edge_kernel<<<(E + 63) / 64, NT, edge_smem>>>(
        nf, ef, src, dst, W1e, b1, lng, lnb, W2, b2,
        Wih_e, Whh_e, bih_e, bhh_e, Wre, bre, out_edges, E);

    node_kernel<<<(N + 63) / 64, NT, node_smem>>>(
        nf, W1n, b1, lng, lnb, W2, b2,
        Wih_a, Whh_a, bih_a, bhh_a, Wra, bra, out_nodes, N);
}